// round 1
// baseline (speedup 1.0000x reference)
#include <cuda_runtime.h>
#include <math.h>

#define BB 64
#define TT 256
#define EE 300
#define UU 512
#define GG 2048
#define TBT (BB*TT)     /* 16384 rows per direction */
#define M2  (2*TBT)     /* 32768 total rows */

// ---------------- device scratch (static allocation only) ----------------
__device__ float g_z[(size_t)M2 * GG];            // [2][B][T][4U]  268 MB
__device__ float g_hall1[(size_t)2 * TBT * UU];   // [2][B][T][U]   67 MB
__device__ float g_hall2[(size_t)2 * TBT * UU];   // [2][B][T][U]   67 MB
__device__ float g_c[2 * BB * UU];                // cell state
__device__ float g_enc[(size_t)TBT * UU];         // [B][T][U]
__device__ float g_scores[TBT];                   // [B][T]
__device__ float g_pooled[BB * UU];               // [B][U]

__device__ __forceinline__ float sigf(float x) { return 1.f / (1.f + expf(-x)); }
__device__ __forceinline__ float ssf(float x)  { return x / (1.f + fabsf(x)); }

// ---------------- big GEMM: out = A @ Bmat + bias -> g_z ----------------
// A rows indexed m in [0, 32768): d = m/TBT, then (b,t).
// asel==0: A row = emb[ids[b, t or T-1-t]], K=300
// asel==1: A row = g_hall1 + m*U, K=512
// asel==2: A row = g_hall2 + m*U, K=512
__global__ __launch_bounds__(256) void gemm_big(
    const int* __restrict__ ids, const float* __restrict__ emb,
    const float* __restrict__ Bbase, long Bstride,
    const float* __restrict__ biasBase, long biasStride,
    int K, int asel)
{
    const int m0 = blockIdx.x * 64;
    const int n0 = blockIdx.y * 64;
    const int d  = m0 / TBT;
    const float* Bmat = Bbase + (long)d * Bstride;
    const float* bias = biasBase + (long)d * biasStride;

    __shared__ float As[8][72];
    __shared__ float Bs[8][64];
    __shared__ const float* rowp[64];

    const int tid = threadIdx.x;
    if (tid < 64) {
        int m = m0 + tid;
        if (asel == 0) {
            int bt = m % TBT;
            int b = bt / TT, t = bt % TT;
            int tt = d ? (TT - 1 - t) : t;
            rowp[tid] = emb + (long)ids[b * TT + tt] * EE;
        } else {
            const float* hall = (asel == 1) ? g_hall1 : g_hall2;
            rowp[tid] = hall + (long)m * UU;
        }
    }
    __syncthreads();

    const int ty = tid >> 4, tx = tid & 15;
    float acc[4][4] = {};

    for (int kb = 0; kb < K; kb += 8) {
        #pragma unroll
        for (int i = tid; i < 64 * 8; i += 256) {
            int mm = i >> 3, kk = i & 7;
            int k = kb + kk;
            As[kk][mm] = (k < K) ? rowp[mm][k] : 0.f;
        }
        #pragma unroll
        for (int i = tid; i < 8 * 64; i += 256) {
            int kk = i >> 6, nn = i & 63;
            int k = kb + kk;
            Bs[kk][nn] = (k < K) ? Bmat[(long)k * GG + n0 + nn] : 0.f;
        }
        __syncthreads();
        #pragma unroll
        for (int kk = 0; kk < 8; kk++) {
            float a0 = As[kk][ty*4+0], a1 = As[kk][ty*4+1];
            float a2 = As[kk][ty*4+2], a3 = As[kk][ty*4+3];
            float b0v = Bs[kk][tx*4+0], b1v = Bs[kk][tx*4+1];
            float b2v = Bs[kk][tx*4+2], b3v = Bs[kk][tx*4+3];
            acc[0][0]+=a0*b0v; acc[0][1]+=a0*b1v; acc[0][2]+=a0*b2v; acc[0][3]+=a0*b3v;
            acc[1][0]+=a1*b0v; acc[1][1]+=a1*b1v; acc[1][2]+=a1*b2v; acc[1][3]+=a1*b3v;
            acc[2][0]+=a2*b0v; acc[2][1]+=a2*b1v; acc[2][2]+=a2*b2v; acc[2][3]+=a2*b3v;
            acc[3][0]+=a3*b0v; acc[3][1]+=a3*b1v; acc[3][2]+=a3*b2v; acc[3][3]+=a3*b3v;
        }
        __syncthreads();
    }

    #pragma unroll
    for (int i = 0; i < 4; i++) {
        long m = m0 + ty * 4 + i;
        float* o = g_z + m * GG + n0;
        #pragma unroll
        for (int j = 0; j < 4; j++) {
            int n = tx * 4 + j;
            o[n] = acc[i][j] + bias[n0 + n];
        }
    }
}

// ---------------- one LSTM recurrence timestep ----------------
// z = g_z[d,b,t,:] + h_prev @ rec[d,l];  update c, h; write h into hall[d,b,t,:]
// grid: (unit tiles of 8 = 64, row tiles of 32 = 2, dirs = 2); 128 threads
__global__ __launch_bounds__(128) void lstm_step(
    const float* __restrict__ recLayer, int t, int dstSel)
{
    const int u0 = blockIdx.x * 8;
    const int b0 = blockIdx.y * 32;
    const int d  = blockIdx.z;
    const float* rec = recLayer + (long)d * 3 * UU * GG;
    float* hall = (dstSel == 1) ? g_hall1 : g_hall2;

    __shared__ float As[32][33];
    __shared__ float Bs[32][36];
    __shared__ float Zs[32][36];

    const int tid = threadIdx.x;
    const int rg = tid >> 4;   // 8 row groups x 4 rows
    const int cg = tid & 15;   // 16 col groups x 2 cols
    float acc[4][2] = {};

    const float* hp = hall + ((long)d * TBT + (long)b0 * TT + (t - 1)) * UU;

    for (int kb = 0; kb < UU; kb += 32) {
        for (int i = tid; i < 32 * 32; i += 128) {
            int r = i >> 5, kk = i & 31;
            float v = 0.f;
            if (t > 0) v = hp[(long)r * TT * UU + kb + kk];
            As[r][kk] = v;
        }
        for (int i = tid; i < 32 * 32; i += 128) {
            int kk = i >> 5, c = i & 31;
            int gcol = (c >> 3) * UU + u0 + (c & 7);   // gate = c/8, unit = u0 + c%8
            Bs[kk][c] = rec[(long)(kb + kk) * GG + gcol];
        }
        __syncthreads();
        #pragma unroll
        for (int kk = 0; kk < 32; kk++) {
            float bv0 = Bs[kk][cg * 2], bv1 = Bs[kk][cg * 2 + 1];
            #pragma unroll
            for (int i = 0; i < 4; i++) {
                float a = As[rg * 4 + i][kk];
                acc[i][0] += a * bv0;
                acc[i][1] += a * bv1;
            }
        }
        __syncthreads();
    }

    #pragma unroll
    for (int i = 0; i < 4; i++) {
        Zs[rg * 4 + i][cg * 2]     = acc[i][0];
        Zs[rg * 4 + i][cg * 2 + 1] = acc[i][1];
    }
    __syncthreads();

    for (int item = tid; item < 256; item += 128) {
        int r = item >> 3, j = item & 7;
        int b = b0 + r;
        int u = u0 + j;
        long row = (long)d * TBT + (long)b * TT + t;
        const float* zin = g_z + row * GG;
        float iz = Zs[r][j]      + zin[u];
        float fz = Zs[r][8 + j]  + zin[UU + u];
        float gz = Zs[r][16 + j] + zin[2 * UU + u];
        float oz = Zs[r][24 + j] + zin[3 * UU + u];
        long cidx = ((long)d * BB + b) * UU + u;
        float cn = sigf(fz) * g_c[cidx] + sigf(iz) * ssf(gz);
        g_c[cidx] = cn;
        hall[row * UU + u] = sigf(oz) * ssf(cn);
    }
}

__global__ void zero_c() {
    int i = blockIdx.x * blockDim.x + threadIdx.x;
    if (i < 2 * BB * UU) g_c[i] = 0.f;
}

__global__ void enc_avg() {
    size_t i = (size_t)blockIdx.x * blockDim.x + threadIdx.x;
    if (i < (size_t)TBT * UU)
        g_enc[i] = 0.5f * (g_hall1[i] + g_hall1[(size_t)TBT * UU + i]);
}

// ---------------- attention scores: prelu(enc@Wa0+ba0) @ Wa1 + ba1 ----------------
// grid (B, T/16), 256 threads (thread = hidden j)
__global__ __launch_bounds__(256) void att_scores(
    const float* __restrict__ Wa0, const float* __restrict__ ba0,
    const float* __restrict__ alpha_a, const float* __restrict__ Wa1,
    const float* __restrict__ ba1)
{
    const int b = blockIdx.x;
    const int t0 = blockIdx.y * 16;
    __shared__ float encsT[512][16];
    __shared__ float red[256];
    const int tid = threadIdx.x;

    for (int i = tid; i < 16 * 512; i += 256) {
        int tt = i >> 9, u = i & 511;
        encsT[u][tt] = g_enc[((size_t)b * TT + t0 + tt) * UU + u];
    }
    __syncthreads();

    float a[16];
    float bb = ba0[tid];
    #pragma unroll
    for (int q = 0; q < 16; q++) a[q] = bb;

    for (int u = 0; u < 512; u++) {
        float w = Wa0[u * 256 + tid];
        const float4* row = (const float4*)encsT[u];
        float4 e0 = row[0], e1 = row[1], e2 = row[2], e3 = row[3];
        a[0]  += e0.x * w; a[1]  += e0.y * w; a[2]  += e0.z * w; a[3]  += e0.w * w;
        a[4]  += e1.x * w; a[5]  += e1.y * w; a[6]  += e1.z * w; a[7]  += e1.w * w;
        a[8]  += e2.x * w; a[9]  += e2.y * w; a[10] += e2.z * w; a[11] += e2.w * w;
        a[12] += e3.x * w; a[13] += e3.y * w; a[14] += e3.z * w; a[15] += e3.w * w;
    }

    float al = alpha_a[tid], w1 = Wa1[tid], b1v = ba1[0];
    for (int q = 0; q < 16; q++) {
        float v = a[q];
        v = (v >= 0.f) ? v : al * v;
        v *= w1;
        red[tid] = v; __syncthreads();
        for (int s = 128; s > 0; s >>= 1) {
            if (tid < s) red[tid] += red[tid + s];
            __syncthreads();
        }
        if (tid == 0) g_scores[b * TT + t0 + q] = red[0] + b1v;
        __syncthreads();
    }
}

// ---------------- softmax over T + weighted pooling ----------------
__global__ __launch_bounds__(256) void softmax_pool() {
    const int b = blockIdx.x;
    const int tid = threadIdx.x;
    __shared__ float ws[256];
    __shared__ float red[256];

    float s = g_scores[b * TT + tid];
    red[tid] = s; __syncthreads();
    for (int st = 128; st > 0; st >>= 1) {
        if (tid < st) red[tid] = fmaxf(red[tid], red[tid + st]);
        __syncthreads();
    }
    float mx = red[0]; __syncthreads();
    float e = expf(s - mx);
    red[tid] = e; __syncthreads();
    for (int st = 128; st > 0; st >>= 1) {
        if (tid < st) red[tid] += red[tid + st];
        __syncthreads();
    }
    float sum = red[0]; __syncthreads();
    ws[tid] = e / sum;
    __syncthreads();

    for (int u = tid; u < UU; u += 256) {
        float acc = 0.f;
        for (int t = 0; t < TT; t++)
            acc += g_enc[((size_t)b * TT + t) * UU + u] * ws[t];
        g_pooled[b * UU + u] = acc;
    }
}

// ---------------- classification head ----------------
__global__ __launch_bounds__(256) void head(
    const float* __restrict__ Wd0, const float* __restrict__ bd0,
    const float* __restrict__ gamma, const float* __restrict__ beta,
    const float* __restrict__ bnm, const float* __restrict__ bnv,
    const float* __restrict__ alpha_h, const float* __restrict__ Wd1,
    const float* __restrict__ bd1, float* __restrict__ out)
{
    const int b = blockIdx.x, j = threadIdx.x;
    __shared__ float ps[512];
    __shared__ float hs[256];
    __shared__ float lgs[7];

    for (int u = j; u < 512; u += 256) ps[u] = g_pooled[b * UU + u];
    __syncthreads();

    float h = bd0[j];
    for (int u = 0; u < 512; u++) h += ps[u] * Wd0[u * 256 + j];
    h = (h - bnm[j]) * rsqrtf(bnv[j] + 1e-3f) * gamma[j] + beta[j];
    h = (h >= 0.f) ? h : alpha_h[j] * h;
    hs[j] = h;
    __syncthreads();

    if (j < 7) {
        float lg = bd1[j];
        for (int k = 0; k < 256; k++) lg += hs[k] * Wd1[k * 7 + j];
        lgs[j] = lg;
    }
    __syncthreads();
    if (j == 0) {
        float mx = lgs[0];
        for (int l = 1; l < 7; l++) mx = fmaxf(mx, lgs[l]);
        float sum = 0.f, e[7];
        for (int l = 0; l < 7; l++) { e[l] = expf(lgs[l] - mx); sum += e[l]; }
        for (int l = 0; l < 7; l++) out[b * 7 + l] = e[l] / sum;
    }
}

// ---------------- driver ----------------
extern "C" void kernel_launch(void* const* d_in, const int* in_sizes, int n_in,
                              void* d_out, int out_size)
{
    const int*   ids   = (const int*)  d_in[0];
    const float* emb   = (const float*)d_in[1];
    const float* k0    = (const float*)d_in[2];
    const float* k12   = (const float*)d_in[3];
    const float* rec   = (const float*)d_in[4];
    const float* bias  = (const float*)d_in[5];
    const float* Wa0   = (const float*)d_in[6];
    const float* ba0   = (const float*)d_in[7];
    const float* al_a  = (const float*)d_in[8];
    const float* Wa1   = (const float*)d_in[9];
    const float* ba1   = (const float*)d_in[10];
    const float* Wd0   = (const float*)d_in[11];
    const float* bd0   = (const float*)d_in[12];
    const float* gamma = (const float*)d_in[13];
    const float* beta  = (const float*)d_in[14];
    const float* bnm   = (const float*)d_in[15];
    const float* bnv   = (const float*)d_in[16];
    const float* al_h  = (const float*)d_in[17];
    const float* Wd1   = (const float*)d_in[18];
    const float* bd1   = (const float*)d_in[19];
    float* out = (float*)d_out;

    dim3 ggrid(M2 / 64, GG / 64);      // (512, 32)

    // layer-0 input projection (embedding gather fused), both directions
    gemm_big<<<ggrid, 256>>>(ids, emb, k0, (long)EE * GG, bias, (long)3 * GG, EE, 0);

    for (int l = 0; l < 3; l++) {
        if (l == 1)
            gemm_big<<<ggrid, 256>>>(ids, emb, k12, (long)2 * UU * GG,
                                     bias + GG, (long)3 * GG, UU, 1);
        if (l == 2)
            gemm_big<<<ggrid, 256>>>(ids, emb, k12 + (long)UU * GG, (long)2 * UU * GG,
                                     bias + 2 * GG, (long)3 * GG, UU, 2);
        zero_c<<<64, 1024>>>();
        int dst = (l == 1) ? 2 : 1;
        const float* recLayer = rec + (long)l * UU * GG;
        for (int t = 0; t < TT; t++)
            lstm_step<<<dim3(64, 2, 2), 128>>>(recLayer, t, dst);
    }

    enc_avg<<<(int)(((size_t)TBT * UU + 255) / 256), 256>>>();
    att_scores<<<dim3(BB, TT / 16), 256>>>(Wa0, ba0, al_a, Wa1, ba1);
    softmax_pool<<<BB, 256>>>();
    head<<<BB, 256>>>(Wd0, bd0, gamma, beta, bnm, bnv, al_h, Wd1, bd1, out);
}

// round 3
// speedup vs baseline: 3.3278x; 3.3278x over previous
#include <cuda_runtime.h>
#include <math.h>
#include <stdint.h>

#define BB 64
#define TT 256
#define EE 300
#define UU 512
#define GG 2048
#define TBT (BB*TT)     /* 16384 rows per direction */
#define M2  (2*TBT)     /* 32768 total rows */

// ---------------- device scratch (static allocation only) ----------------
__device__ float g_z[(size_t)M2 * GG];            // [2][B][T][4U]
__device__ float g_hall1[(size_t)2 * TBT * UU];   // [2][B][T][U]
__device__ float g_hall2[(size_t)2 * TBT * UU];   // [2][B][T][U]
__device__ float g_enc[(size_t)TBT * UU];         // [B][T][U]
__device__ float g_scores[TBT];                   // [B][T]
__device__ float g_pooled[BB * UU];               // [B][U]
__device__ int   g_cnt[2 * TT];                   // per-dir per-step arrival counters

__device__ __forceinline__ float sigf(float x) { return 1.f / (1.f + expf(-x)); }
__device__ __forceinline__ float ssf(float x)  { return x / (1.f + fabsf(x)); }

__device__ __forceinline__ float to_tf32(float x) {
    uint32_t u; asm("cvt.rna.tf32.f32 %0, %1;" : "=r"(u) : "f"(x));
    return __uint_as_float(u);
}
__device__ __forceinline__ uint32_t fu(float x) { return __float_as_uint(x); }

#define MMA_TF32(d0,d1,d2,d3,a0,a1,a2,a3,b0,b1) \
    asm volatile("mma.sync.aligned.m16n8k8.row.col.f32.tf32.tf32.f32 " \
        "{%0,%1,%2,%3}, {%4,%5,%6,%7}, {%8,%9}, {%0,%1,%2,%3};" \
        : "+f"(d0), "+f"(d1), "+f"(d2), "+f"(d3) \
        : "r"(a0), "r"(a1), "r"(a2), "r"(a3), "r"(b0), "r"(b1))

// ================= big GEMM via tf32 mma: g_z = A @ Bmat + bias =================
// Block tile 128x64, 256 threads (8 warps), K-chunks of 32.
// Warp w: rows (w>>1)*32 (2 m-tiles of 16), cols (w&1)*32 (4 n-tiles of 8).
// asel==0: A row = emb[ids[b, t or T-1-t]], K=300
// asel==1: A row = g_hall1 + m*U, K=512
// asel==2: A row = g_hall2 + m*U, K=512
__global__ __launch_bounds__(256) void gemm_mma(
    const int* __restrict__ ids, const float* __restrict__ emb,
    const float* __restrict__ Bbase, long Bstride,
    const float* __restrict__ biasBase, long biasStride,
    int K, int asel)
{
    __shared__ float As[128 * 36];
    __shared__ float Bs[32 * 72];          // 64 cols + 8 pad  (R2 bug: was 40)
    __shared__ const float* rowp[128];

    const int m0 = blockIdx.x * 128;
    const int n0 = blockIdx.y * 64;
    const int d  = m0 / TBT;
    const float* Bmat = Bbase + (long)d * Bstride;
    const float* bias = biasBase + (long)d * biasStride;
    const int tid = threadIdx.x;

    if (tid < 128) {
        int m = m0 + tid;
        if (asel == 0) {
            int bt = m % TBT;
            int b = bt / TT, t = bt % TT;
            int tt = d ? (TT - 1 - t) : t;
            rowp[tid] = emb + (long)ids[b * TT + tt] * EE;
        } else {
            const float* hall = (asel == 1) ? g_hall1 : g_hall2;
            rowp[tid] = hall + (long)m * UU;
        }
    }
    __syncthreads();

    const int w = tid >> 5, lane = tid & 31;
    const int g = lane >> 2, t4 = lane & 3;
    const int mw = (w >> 1) * 32;
    const int nw = (w & 1) * 32;

    float acc[2][4][4];
    #pragma unroll
    for (int a = 0; a < 2; a++)
        #pragma unroll
        for (int b = 0; b < 4; b++)
            #pragma unroll
            for (int c = 0; c < 4; c++) acc[a][b][c] = 0.f;

    float4 aP[4], bP[2];
    const int nch = (K + 31) >> 5;

    // ---- prefetch loaders ----
    auto ldA = [&](int kb) {
        bool full = (kb + 32) <= K;
        #pragma unroll
        for (int i = 0; i < 4; i++) {
            int idx = tid + i * 256;          // 0..1023 float4s
            int row = idx >> 3, c4 = idx & 7;
            if (full) {
                aP[i] = *(const float4*)(rowp[row] + kb + c4 * 4);
            } else {
                float v[4];
                #pragma unroll
                for (int q = 0; q < 4; q++) {
                    int k = kb + c4 * 4 + q;
                    v[q] = (k < K) ? rowp[row][k] : 0.f;
                }
                aP[i] = make_float4(v[0], v[1], v[2], v[3]);
            }
        }
    };
    auto ldB = [&](int kb) {
        #pragma unroll
        for (int i = 0; i < 2; i++) {
            int idx = tid + i * 256;          // 0..511 float4s
            int kr = idx >> 4, c4 = idx & 15;
            int k = kb + kr;
            if (k < K) bP[i] = *(const float4*)(Bmat + (long)k * GG + n0 + c4 * 4);
            else       bP[i] = make_float4(0.f, 0.f, 0.f, 0.f);
        }
    };

    ldA(0); ldB(0);

    for (int c = 0; c < nch; c++) {
        __syncthreads();
        #pragma unroll
        for (int i = 0; i < 4; i++) {
            int idx = tid + i * 256;
            int row = idx >> 3, c4 = idx & 7;
            float4 v = aP[i];
            *(float4*)&As[row * 36 + c4 * 4] =
                make_float4(to_tf32(v.x), to_tf32(v.y), to_tf32(v.z), to_tf32(v.w));
        }
        #pragma unroll
        for (int i = 0; i < 2; i++) {
            int idx = tid + i * 256;
            int kr = idx >> 4, c4 = idx & 15;
            float4 v = bP[i];
            *(float4*)&Bs[kr * 72 + c4 * 4] =
                make_float4(to_tf32(v.x), to_tf32(v.y), to_tf32(v.z), to_tf32(v.w));
        }
        __syncthreads();
        if (c + 1 < nch) { ldA((c + 1) * 32); ldB((c + 1) * 32); }

        #pragma unroll
        for (int kk = 0; kk < 32; kk += 8) {
            uint32_t a[2][4];
            #pragma unroll
            for (int mt = 0; mt < 2; mt++) {
                int rb = mw + mt * 16;
                a[mt][0] = fu(As[(rb + g)     * 36 + kk + t4]);
                a[mt][1] = fu(As[(rb + 8 + g) * 36 + kk + t4]);
                a[mt][2] = fu(As[(rb + g)     * 36 + kk + t4 + 4]);
                a[mt][3] = fu(As[(rb + 8 + g) * 36 + kk + t4 + 4]);
            }
            #pragma unroll
            for (int nt = 0; nt < 4; nt++) {
                uint32_t b0 = fu(Bs[(kk + t4)     * 72 + nw + nt * 8 + g]);
                uint32_t b1 = fu(Bs[(kk + t4 + 4) * 72 + nw + nt * 8 + g]);
                MMA_TF32(acc[0][nt][0], acc[0][nt][1], acc[0][nt][2], acc[0][nt][3],
                         a[0][0], a[0][1], a[0][2], a[0][3], b0, b1);
                MMA_TF32(acc[1][nt][0], acc[1][nt][1], acc[1][nt][2], acc[1][nt][3],
                         a[1][0], a[1][1], a[1][2], a[1][3], b0, b1);
            }
        }
    }

    // epilogue: + bias -> g_z
    #pragma unroll
    for (int mt = 0; mt < 2; mt++) {
        #pragma unroll
        for (int nt = 0; nt < 4; nt++) {
            int col = n0 + nw + nt * 8 + 2 * t4;
            float b0 = bias[col], b1 = bias[col + 1];
            long r0 = (long)m0 + mw + mt * 16 + g;
            *(float2*)&g_z[r0 * GG + col] =
                make_float2(acc[mt][nt][0] + b0, acc[mt][nt][1] + b1);
            *(float2*)&g_z[(r0 + 8) * GG + col] =
                make_float2(acc[mt][nt][2] + b0, acc[mt][nt][3] + b1);
        }
    }
}

// ================= persistent LSTM layer (all 256 timesteps in one launch) ======
// grid = 128 blocks: d = bx>>6, unit-slice cb = bx&63 (8 units -> 32 gate cols).
// 256 threads = 8 warps; C tile 64(batch) x 32(cols): m-tiles 4, n-tiles 4;
// warp w: mi = w>>1, n-tile pair njp = w&1.
// SMEM: Ws[512][40] weights (tf32, resident whole launch), As[64][516] h_{t-1},
//       Cs[64][33] mma result, cellc[64][8] cell state.
#define LSTM_SMEM_BYTES ((512*40 + 64*516 + 64*33 + 64*8) * 4)

__global__ __launch_bounds__(256) void lstm_layer(
    const float* __restrict__ recLayer,   // rec + l*U*GG  (dir stride 3*U*GG)
    float* __restrict__ hallOut)
{
    extern __shared__ float sm[];
    float* Ws    = sm;                       // 512*40
    float* As    = Ws + 512 * 40;            // 64*516
    float* Cs    = As + 64 * 516;            // 64*33
    float* cellc = Cs + 64 * 33;             // 64*8

    const int bx = blockIdx.x;
    const int d  = bx >> 6;
    const int u0 = (bx & 63) * 8;
    const float* rec = recLayer + (long)d * 3 * UU * GG;
    const int tid = threadIdx.x;

    // weights: Ws[k][gate*8+j] = rec[k][gate*512 + u0 + j], tf32-rounded
    for (int i = tid; i < 512 * 32; i += 256) {
        int k = i >> 5, c = i & 31;
        int gate = c >> 3, j = c & 7;
        Ws[k * 40 + c] = to_tf32(rec[(long)k * GG + gate * UU + u0 + j]);
    }
    for (int i = tid; i < 64 * 8; i += 256) cellc[i] = 0.f;
    __syncthreads();

    const int w = tid >> 5, lane = tid & 31;
    const int g = lane >> 2, t4 = lane & 3;
    const int mi = w >> 1;      // 0..3
    const int njp = w & 1;      // n-tile pair

    const int r0e = tid >> 3;           // epilogue rows
    const int je  = tid & 7;

    for (int t = 0; t < TT; t++) {
        // ---- wait for h_{t-1} from all 64 blocks of this dir ----
        if (t > 0) {
            if (tid == 0) {
                volatile int* p = &g_cnt[d * TT + (t - 1)];
                while (*p < 64) __nanosleep(64);
                __threadfence();
            }
            __syncthreads();
        }

        // ---- stage A = h_{t-1} [64][512] (zeros at t==0) ----
        if (t == 0) {
            for (int i = tid; i < 64 * 516; i += 256) As[i] = 0.f;
        } else {
            const float* hb = hallOut + ((long)d * TBT + (t - 1)) * (long)UU;
            #pragma unroll
            for (int i = 0; i < 32; i++) {
                int idx = tid + i * 256;
                int row = idx >> 7, c4 = idx & 127;
                float4 v = *(const float4*)(hb + (long)row * TT * UU + c4 * 4);
                *(float4*)&As[row * 516 + c4 * 4] =
                    make_float4(to_tf32(v.x), to_tf32(v.y), to_tf32(v.z), to_tf32(v.w));
            }
        }
        __syncthreads();

        // ---- prefetch z for epilogue (hide L2 latency under mma) ----
        long zr0 = ((long)d * TBT + (long)r0e * TT + t) * GG + u0 + je;
        long zr1 = zr0 + (long)32 * TT * GG;
        float z0i = g_z[zr0], z0f = g_z[zr0 + UU], z0g = g_z[zr0 + 2*UU], z0o = g_z[zr0 + 3*UU];
        float z1i = g_z[zr1], z1f = g_z[zr1 + UU], z1g = g_z[zr1 + 2*UU], z1o = g_z[zr1 + 3*UU];

        // ---- mma: [64x512] @ [512x32] ----
        float acc[2][4] = {{0.f,0.f,0.f,0.f},{0.f,0.f,0.f,0.f}};
        const int arb0 = (mi * 16 + g) * 516;
        const int arb1 = arb0 + 8 * 516;
        #pragma unroll 8
        for (int kk = 0; kk < 512; kk += 8) {
            uint32_t a0 = fu(As[arb0 + kk + t4]);
            uint32_t a1 = fu(As[arb1 + kk + t4]);
            uint32_t a2 = fu(As[arb0 + kk + t4 + 4]);
            uint32_t a3 = fu(As[arb1 + kk + t4 + 4]);
            #pragma unroll
            for (int s = 0; s < 2; s++) {
                int nb = (njp * 2 + s) * 8 + g;
                uint32_t b0 = fu(Ws[(kk + t4)     * 40 + nb]);
                uint32_t b1 = fu(Ws[(kk + t4 + 4) * 40 + nb]);
                MMA_TF32(acc[s][0], acc[s][1], acc[s][2], acc[s][3],
                         a0, a1, a2, a3, b0, b1);
            }
        }

        // ---- dump fragments to Cs ----
        #pragma unroll
        for (int s = 0; s < 2; s++) {
            int colb = (njp * 2 + s) * 8 + 2 * t4;
            int rw = mi * 16 + g;
            Cs[rw * 33 + colb]           = acc[s][0];
            Cs[rw * 33 + colb + 1]       = acc[s][1];
            Cs[(rw + 8) * 33 + colb]     = acc[s][2];
            Cs[(rw + 8) * 33 + colb + 1] = acc[s][3];
        }
        __syncthreads();

        // ---- gate epilogue: 2 items per thread ----
        {
            int r = r0e;
            float iz = Cs[r * 33 + je]      + z0i;
            float fz = Cs[r * 33 + 8 + je]  + z0f;
            float gz = Cs[r * 33 + 16 + je] + z0g;
            float oz = Cs[r * 33 + 24 + je] + z0o;
            float cn = sigf(fz) * cellc[r * 8 + je] + sigf(iz) * ssf(gz);
            cellc[r * 8 + je] = cn;
            hallOut[((long)d * TBT + (long)r * TT + t) * UU + u0 + je] = sigf(oz) * ssf(cn);
        }
        {
            int r = r0e + 32;
            float iz = Cs[r * 33 + je]      + z1i;
            float fz = Cs[r * 33 + 8 + je]  + z1f;
            float gz = Cs[r * 33 + 16 + je] + z1g;
            float oz = Cs[r * 33 + 24 + je] + z1o;
            float cn = sigf(fz) * cellc[r * 8 + je] + sigf(iz) * ssf(gz);
            cellc[r * 8 + je] = cn;
            hallOut[((long)d * TBT + (long)r * TT + t) * UU + u0 + je] = sigf(oz) * ssf(cn);
        }

        // ---- signal h_t complete ----
        __threadfence();
        __syncthreads();
        if (tid == 0) atomicAdd(&g_cnt[d * TT + t], 1);
    }
}

__global__ void zero_cnt() {
    int i = blockIdx.x * 256 + threadIdx.x;
    if (i < 2 * TT) g_cnt[i] = 0;
}

__global__ void enc_avg() {
    size_t i = (size_t)blockIdx.x * blockDim.x + threadIdx.x;
    if (i < (size_t)TBT * UU)
        g_enc[i] = 0.5f * (g_hall1[i] + g_hall1[(size_t)TBT * UU + i]);
}

// ---------------- attention scores: prelu(enc@Wa0+ba0) @ Wa1 + ba1 ----------------
__global__ __launch_bounds__(256) void att_scores(
    const float* __restrict__ Wa0, const float* __restrict__ ba0,
    const float* __restrict__ alpha_a, const float* __restrict__ Wa1,
    const float* __restrict__ ba1)
{
    const int b = blockIdx.x;
    const int t0 = blockIdx.y * 16;
    __shared__ float encsT[512][16];
    __shared__ float red[256];
    const int tid = threadIdx.x;

    for (int i = tid; i < 16 * 512; i += 256) {
        int tt = i >> 9, u = i & 511;
        encsT[u][tt] = g_enc[((size_t)b * TT + t0 + tt) * UU + u];
    }
    __syncthreads();

    float a[16];
    float bb = ba0[tid];
    #pragma unroll
    for (int q = 0; q < 16; q++) a[q] = bb;

    for (int u = 0; u < 512; u++) {
        float w = Wa0[u * 256 + tid];
        const float4* row = (const float4*)encsT[u];
        float4 e0 = row[0], e1 = row[1], e2 = row[2], e3 = row[3];
        a[0]  += e0.x * w; a[1]  += e0.y * w; a[2]  += e0.z * w; a[3]  += e0.w * w;
        a[4]  += e1.x * w; a[5]  += e1.y * w; a[6]  += e1.z * w; a[7]  += e1.w * w;
        a[8]  += e2.x * w; a[9]  += e2.y * w; a[10] += e2.z * w; a[11] += e2.w * w;
        a[12] += e3.x * w; a[13] += e3.y * w; a[14] += e3.z * w; a[15] += e3.w * w;
    }

    float al = alpha_a[tid], w1 = Wa1[tid], b1v = ba1[0];
    for (int q = 0; q < 16; q++) {
        float v = a[q];
        v = (v >= 0.f) ? v : al * v;
        v *= w1;
        red[tid] = v; __syncthreads();
        for (int s = 128; s > 0; s >>= 1) {
            if (tid < s) red[tid] += red[tid + s];
            __syncthreads();
        }
        if (tid == 0) g_scores[b * TT + t0 + q] = red[0] + b1v;
        __syncthreads();
    }
}

// ---------------- softmax over T + weighted pooling ----------------
__global__ __launch_bounds__(256) void softmax_pool() {
    const int b = blockIdx.x;
    const int tid = threadIdx.x;
    __shared__ float ws[256];
    __shared__ float red[256];

    float s = g_scores[b * TT + tid];
    red[tid] = s; __syncthreads();
    for (int st = 128; st > 0; st >>= 1) {
        if (tid < st) red[tid] = fmaxf(red[tid], red[tid + st]);
        __syncthreads();
    }
    float mx = red[0]; __syncthreads();
    float e = expf(s - mx);
    red[tid] = e; __syncthreads();
    for (int st = 128; st > 0; st >>= 1) {
        if (tid < st) red[tid] += red[tid + st];
        __syncthreads();
    }
    float sum = red[0]; __syncthreads();
    ws[tid] = e / sum;
    __syncthreads();

    for (int u = tid; u < UU; u += 256) {
        float acc = 0.f;
        for (int t = 0; t < TT; t++)
            acc += g_enc[((size_t)b * TT + t) * UU + u] * ws[t];
        g_pooled[b * UU + u] = acc;
    }
}

// ---------------- classification head ----------------
__global__ __launch_bounds__(256) void head(
    const float* __restrict__ Wd0, const float* __restrict__ bd0,
    const float* __restrict__ gamma, const float* __restrict__ beta,
    const float* __restrict__ bnm, const float* __restrict__ bnv,
    const float* __restrict__ alpha_h, const float* __restrict__ Wd1,
    const float* __restrict__ bd1, float* __restrict__ out)
{
    const int b = blockIdx.x, j = threadIdx.x;
    __shared__ float ps[512];
    __shared__ float hs[256];
    __shared__ float lgs[7];

    for (int u = j; u < 512; u += 256) ps[u] = g_pooled[b * UU + u];
    __syncthreads();

    float h = bd0[j];
    for (int u = 0; u < 512; u++) h += ps[u] * Wd0[u * 256 + j];
    h = (h - bnm[j]) * rsqrtf(bnv[j] + 1e-3f) * gamma[j] + beta[j];
    h = (h >= 0.f) ? h : alpha_h[j] * h;
    hs[j] = h;
    __syncthreads();

    if (j < 7) {
        float lg = bd1[j];
        for (int k = 0; k < 256; k++) lg += hs[k] * Wd1[k * 7 + j];
        lgs[j] = lg;
    }
    __syncthreads();
    if (j == 0) {
        float mx = lgs[0];
        for (int l = 1; l < 7; l++) mx = fmaxf(mx, lgs[l]);
        float sum = 0.f, e[7];
        for (int l = 0; l < 7; l++) { e[l] = expf(lgs[l] - mx); sum += e[l]; }
        for (int l = 0; l < 7; l++) out[b * 7 + l] = e[l] / sum;
    }
}

// ---------------- driver ----------------
extern "C" void kernel_launch(void* const* d_in, const int* in_sizes, int n_in,
                              void* d_out, int out_size)
{
    const int*   ids   = (const int*)  d_in[0];
    const float* emb   = (const float*)d_in[1];
    const float* k0    = (const float*)d_in[2];
    const float* k12   = (const float*)d_in[3];
    const float* rec   = (const float*)d_in[4];
    const float* bias  = (const float*)d_in[5];
    const float* Wa0   = (const float*)d_in[6];
    const float* ba0   = (const float*)d_in[7];
    const float* al_a  = (const float*)d_in[8];
    const float* Wa1   = (const float*)d_in[9];
    const float* ba1   = (const float*)d_in[10];
    const float* Wd0   = (const float*)d_in[11];
    const float* bd0   = (const float*)d_in[12];
    const float* gamma = (const float*)d_in[13];
    const float* beta  = (const float*)d_in[14];
    const float* bnm   = (const float*)d_in[15];
    const float* bnv   = (const float*)d_in[16];
    const float* al_h  = (const float*)d_in[17];
    const float* Wd1   = (const float*)d_in[18];
    const float* bd1   = (const float*)d_in[19];
    float* out = (float*)d_out;

    cudaFuncSetAttribute((const void*)lstm_layer,
                         cudaFuncAttributeMaxDynamicSharedMemorySize, LSTM_SMEM_BYTES);

    dim3 ggrid(M2 / 128, GG / 64);   // (256, 32)

    // layer-0 input projection (embedding gather fused), both directions
    gemm_mma<<<ggrid, 256>>>(ids, emb, k0, (long)EE * GG, bias, (long)3 * GG, EE, 0);

    for (int l = 0; l < 3; l++) {
        if (l == 1)
            gemm_mma<<<ggrid, 256>>>(ids, emb, k12, (long)2 * UU * GG,
                                     bias + GG, (long)3 * GG, UU, 1);
        if (l == 2)
            gemm_mma<<<ggrid, 256>>>(ids, emb, k12 + (long)UU * GG, (long)2 * UU * GG,
                                     bias + 2 * GG, (long)3 * GG, UU, 2);
        zero_cnt<<<2, 256>>>();
        float* dstp; cudaGetSymbolAddress((void**)&dstp, (l == 1) ? g_hall2 : g_hall1);
        lstm_layer<<<128, 256, LSTM_SMEM_BYTES>>>(rec + (long)l * UU * GG, dstp);
    }

    enc_avg<<<(int)(((size_t)TBT * UU + 255) / 256), 256>>>();
    att_scores<<<dim3(BB, TT / 16), 256>>>(Wa0, ba0, al_a, Wa1, ba1);
    softmax_pool<<<BB, 256>>>();
    head<<<BB, 256>>>(Wd0, bd0, gamma, beta, bnm, bnv, al_h, Wd1, bd1, out);
}

// round 4
// speedup vs baseline: 3.7042x; 1.1131x over previous
#include <cuda_runtime.h>
#include <cuda_bf16.h>
#include <math.h>
#include <stdint.h>

#define BB 64
#define TT 256
#define EE 300
#define UU 512
#define GG 2048
#define TBT (BB*TT)     /* 16384 rows per direction */
#define M2  (2*TBT)     /* 32768 total rows */

// ---------------- device scratch (static allocation only) ----------------
__device__ float g_z[(size_t)M2 * GG];            // [2][B][T][4U]
__device__ float g_hall1[(size_t)2 * TBT * UU];   // [2][B][T][U]
__device__ float g_hall2[(size_t)2 * TBT * UU];   // [2][B][T][U]
__device__ float g_enc[(size_t)TBT * UU];         // [B][T][U]
__device__ float g_scores[TBT];                   // [B][T]
__device__ float g_pooled[BB * UU];               // [B][U]
__device__ int   g_cnt[2 * TT];                   // per-dir per-step arrival counters
__device__ __nv_bfloat16 g_hbf[2 * 2 * BB * UU];  // [dir][parity][B][U] bf16 h

__device__ __forceinline__ float sigf(float x) { return 1.f / (1.f + __expf(-x)); }
__device__ __forceinline__ float ssf(float x)  { return x / (1.f + fabsf(x)); }

__device__ __forceinline__ float to_tf32(float x) {
    uint32_t u; asm("cvt.rna.tf32.f32 %0, %1;" : "=r"(u) : "f"(x));
    return __uint_as_float(u);
}
__device__ __forceinline__ uint32_t fu(float x) { return __float_as_uint(x); }

#define MMA_TF32(d0,d1,d2,d3,a0,a1,a2,a3,b0,b1) \
    asm volatile("mma.sync.aligned.m16n8k8.row.col.f32.tf32.tf32.f32 " \
        "{%0,%1,%2,%3}, {%4,%5,%6,%7}, {%8,%9}, {%0,%1,%2,%3};" \
        : "+f"(d0), "+f"(d1), "+f"(d2), "+f"(d3) \
        : "r"(a0), "r"(a1), "r"(a2), "r"(a3), "r"(b0), "r"(b1))

#define MMA_BF16(d0,d1,d2,d3,a0,a1,a2,a3,b0,b1) \
    asm volatile("mma.sync.aligned.m16n8k16.row.col.f32.bf16.bf16.f32 " \
        "{%0,%1,%2,%3}, {%4,%5,%6,%7}, {%8,%9}, {%0,%1,%2,%3};" \
        : "+f"(d0), "+f"(d1), "+f"(d2), "+f"(d3) \
        : "r"(a0), "r"(a1), "r"(a2), "r"(a3), "r"(b0), "r"(b1))

// ================= big GEMM via tf32 mma: g_z = A @ Bmat + bias =================
__global__ __launch_bounds__(256) void gemm_mma(
    const int* __restrict__ ids, const float* __restrict__ emb,
    const float* __restrict__ Bbase, long Bstride,
    const float* __restrict__ biasBase, long biasStride,
    int K, int asel)
{
    __shared__ float As[128 * 36];
    __shared__ float Bs[32 * 72];
    __shared__ const float* rowp[128];

    const int m0 = blockIdx.x * 128;
    const int n0 = blockIdx.y * 64;
    const int d  = m0 / TBT;
    const float* Bmat = Bbase + (long)d * Bstride;
    const float* bias = biasBase + (long)d * biasStride;
    const int tid = threadIdx.x;

    if (tid < 128) {
        int m = m0 + tid;
        if (asel == 0) {
            int bt = m % TBT;
            int b = bt / TT, t = bt % TT;
            int tt = d ? (TT - 1 - t) : t;
            rowp[tid] = emb + (long)ids[b * TT + tt] * EE;
        } else {
            const float* hall = (asel == 1) ? g_hall1 : g_hall2;
            rowp[tid] = hall + (long)m * UU;
        }
    }
    __syncthreads();

    const int w = tid >> 5, lane = tid & 31;
    const int g = lane >> 2, t4 = lane & 3;
    const int mw = (w >> 1) * 32;
    const int nw = (w & 1) * 32;

    float acc[2][4][4];
    #pragma unroll
    for (int a = 0; a < 2; a++)
        #pragma unroll
        for (int b = 0; b < 4; b++)
            #pragma unroll
            for (int c = 0; c < 4; c++) acc[a][b][c] = 0.f;

    float4 aP[4], bP[2];
    const int nch = (K + 31) >> 5;

    auto ldA = [&](int kb) {
        bool full = (kb + 32) <= K;
        #pragma unroll
        for (int i = 0; i < 4; i++) {
            int idx = tid + i * 256;
            int row = idx >> 3, c4 = idx & 7;
            if (full) {
                aP[i] = *(const float4*)(rowp[row] + kb + c4 * 4);
            } else {
                float v[4];
                #pragma unroll
                for (int q = 0; q < 4; q++) {
                    int k = kb + c4 * 4 + q;
                    v[q] = (k < K) ? rowp[row][k] : 0.f;
                }
                aP[i] = make_float4(v[0], v[1], v[2], v[3]);
            }
        }
    };
    auto ldB = [&](int kb) {
        #pragma unroll
        for (int i = 0; i < 2; i++) {
            int idx = tid + i * 256;
            int kr = idx >> 4, c4 = idx & 15;
            int k = kb + kr;
            if (k < K) bP[i] = *(const float4*)(Bmat + (long)k * GG + n0 + c4 * 4);
            else       bP[i] = make_float4(0.f, 0.f, 0.f, 0.f);
        }
    };

    ldA(0); ldB(0);

    for (int c = 0; c < nch; c++) {
        __syncthreads();
        #pragma unroll
        for (int i = 0; i < 4; i++) {
            int idx = tid + i * 256;
            int row = idx >> 3, c4 = idx & 7;
            float4 v = aP[i];
            *(float4*)&As[row * 36 + c4 * 4] =
                make_float4(to_tf32(v.x), to_tf32(v.y), to_tf32(v.z), to_tf32(v.w));
        }
        #pragma unroll
        for (int i = 0; i < 2; i++) {
            int idx = tid + i * 256;
            int kr = idx >> 4, c4 = idx & 15;
            float4 v = bP[i];
            *(float4*)&Bs[kr * 72 + c4 * 4] =
                make_float4(to_tf32(v.x), to_tf32(v.y), to_tf32(v.z), to_tf32(v.w));
        }
        __syncthreads();
        if (c + 1 < nch) { ldA((c + 1) * 32); ldB((c + 1) * 32); }

        #pragma unroll
        for (int kk = 0; kk < 32; kk += 8) {
            uint32_t a[2][4];
            #pragma unroll
            for (int mt = 0; mt < 2; mt++) {
                int rb = mw + mt * 16;
                a[mt][0] = fu(As[(rb + g)     * 36 + kk + t4]);
                a[mt][1] = fu(As[(rb + 8 + g) * 36 + kk + t4]);
                a[mt][2] = fu(As[(rb + g)     * 36 + kk + t4 + 4]);
                a[mt][3] = fu(As[(rb + 8 + g) * 36 + kk + t4 + 4]);
            }
            #pragma unroll
            for (int nt = 0; nt < 4; nt++) {
                uint32_t b0 = fu(Bs[(kk + t4)     * 72 + nw + nt * 8 + g]);
                uint32_t b1 = fu(Bs[(kk + t4 + 4) * 72 + nw + nt * 8 + g]);
                MMA_TF32(acc[0][nt][0], acc[0][nt][1], acc[0][nt][2], acc[0][nt][3],
                         a[0][0], a[0][1], a[0][2], a[0][3], b0, b1);
                MMA_TF32(acc[1][nt][0], acc[1][nt][1], acc[1][nt][2], acc[1][nt][3],
                         a[1][0], a[1][1], a[1][2], a[1][3], b0, b1);
            }
        }
    }

    #pragma unroll
    for (int mt = 0; mt < 2; mt++) {
        #pragma unroll
        for (int nt = 0; nt < 4; nt++) {
            int col = n0 + nw + nt * 8 + 2 * t4;
            float b0 = bias[col], b1 = bias[col + 1];
            long r0 = (long)m0 + mw + mt * 16 + g;
            *(float2*)&g_z[r0 * GG + col] =
                make_float2(acc[mt][nt][0] + b0, acc[mt][nt][1] + b1);
            *(float2*)&g_z[(r0 + 8) * GG + col] =
                make_float2(acc[mt][nt][2] + b0, acc[mt][nt][3] + b1);
        }
    }
}

// ================= persistent LSTM layer, bf16 mma version =================
// 64 blocks: d = bx>>5, slice = bx&31 -> 16 units (64 gate cols).
// 256 threads = 8 warps. C tile = 64(batch) x 64(gate cols).
// Warp w: mi = w>>1 (batch 16-rows), nq = w&1 (4 of 8 n-tiles).
// SMEM: WsFU  bf16 weight fragments  64KB   (staged once per layer)
//       As16  h_{t-1} bf16 [64][520] 66.5KB (staged per step from g_hbf)
//       Cs    fp32 [64][68]          17.4KB
//       cellc fp32 [64][16]           4KB
#define LSTM_SMEM_BYTES (65536 + 66560 + 17408 + 4096)

__global__ __launch_bounds__(256) void lstm_layer(
    const float* __restrict__ recLayer,   // rec + l*U*GG  (dir stride 3*U*GG)
    float* __restrict__ hallOut)
{
    extern __shared__ char smraw[];
    uint32_t*      WsFU  = (uint32_t*)smraw;                          // 16384 u32
    __nv_bfloat16* As16  = (__nv_bfloat16*)(smraw + 65536);           // 64*520
    uint32_t*      AsU   = (uint32_t*)As16;                           // stride 260
    float*         Cs    = (float*)(smraw + 65536 + 66560);           // 64*68
    float*         cellc = (float*)(smraw + 65536 + 66560 + 17408);   // 64*16

    const int bx = blockIdx.x;
    const int d  = bx >> 5;
    const int u0 = (bx & 31) * 16;
    const float* rec = recLayer + (long)d * 3 * UU * GG;
    const int tid = threadIdx.x;

    // ---- stage weight fragments (once per layer) ----
    // slot i -> chunk cc, ntile nt, lane; stores b0 (k 2t4,2t4+1) and b1 (k+8)
    for (int i = tid; i < 32 * 8 * 32; i += 256) {
        int cc = i >> 8;
        int rem = i & 255;
        int nt = rem >> 5;
        int lane = rem & 31;
        int gq = lane >> 2, t4 = lane & 3;
        int col = nt * 8 + gq;                 // 0..63
        long wcol = (long)(col >> 4) * UU + u0 + (col & 15);
        int k0 = cc * 16 + 2 * t4;
        __nv_bfloat162 b0, b1;
        b0.x = __float2bfloat16_rn(rec[(long)k0 * GG + wcol]);
        b0.y = __float2bfloat16_rn(rec[(long)(k0 + 1) * GG + wcol]);
        b1.x = __float2bfloat16_rn(rec[(long)(k0 + 8) * GG + wcol]);
        b1.y = __float2bfloat16_rn(rec[(long)(k0 + 9) * GG + wcol]);
        uint32_t* dst = WsFU + (((cc * 4 + (nt >> 1)) * 32 + lane) << 2) + (nt & 1) * 2;
        dst[0] = *(uint32_t*)&b0;
        dst[1] = *(uint32_t*)&b1;
    }
    for (int i = tid; i < 64 * 16; i += 256) cellc[i] = 0.f;
    __syncthreads();

    const int w = tid >> 5, lane = tid & 31;
    const int g = lane >> 2, t4 = lane & 3;
    const int mi = w >> 1;        // batch 16-row tile
    const int nq = w & 1;         // which 4 n-tiles

    const int be = tid & 63;      // epilogue batch row
    const int jq = tid >> 6;      // epilogue unit quad (4 units)

    for (int t = 0; t < TT; t++) {
        // ---- prefetch z for this step (independent of barrier) ----
        long zbase = ((long)d * TBT + (long)be * TT + t) * GG + u0 + jq * 4;
        float4 zi = *(const float4*)&g_z[zbase];
        float4 zf = *(const float4*)&g_z[zbase + UU];
        float4 zg = *(const float4*)&g_z[zbase + 2 * UU];
        float4 zo = *(const float4*)&g_z[zbase + 3 * UU];

        // ---- wait for h_{t-1} from all 32 blocks of this dir ----
        if (t > 0) {
            if (tid == 0) {
                volatile int* p = &g_cnt[d * TT + (t - 1)];
                while (*p < 32) __nanosleep(32);
                __threadfence();
            }
            __syncthreads();
        }

        // ---- stage A = h_{t-1} bf16 [64][512] ----
        if (t == 0) {
            uint4 z4 = make_uint4(0, 0, 0, 0);
            for (int i = tid; i < 64 * 64; i += 256) {
                int row = i >> 6, c8 = i & 63;
                *(uint4*)(As16 + row * 520 + c8 * 8) = z4;
            }
        } else {
            const int par = (t - 1) & 1;
            const __nv_bfloat16* hb = g_hbf + ((long)(d * 2 + par) * BB) * UU;
            #pragma unroll
            for (int i = 0; i < 16; i++) {
                int idx = tid + i * 256;
                int row = idx >> 6, c8 = idx & 63;
                uint4 v = *(const uint4*)(hb + row * UU + c8 * 8);
                *(uint4*)(As16 + row * 520 + c8 * 8) = v;
            }
        }
        __syncthreads();

        // ---- mma: [64x512] @ [512x64], bf16 m16n8k16 ----
        float acc[4][4];
        #pragma unroll
        for (int q = 0; q < 4; q++)
            #pragma unroll
            for (int r = 0; r < 4; r++) acc[q][r] = 0.f;

        const int ar0 = (mi * 16 + g) * 260;
        const int ar1 = ar0 + 8 * 260;
        #pragma unroll 4
        for (int cc = 0; cc < 32; cc++) {
            uint32_t a0 = AsU[ar0 + cc * 8 + t4];
            uint32_t a1 = AsU[ar1 + cc * 8 + t4];
            uint32_t a2 = AsU[ar0 + cc * 8 + t4 + 4];
            uint32_t a3 = AsU[ar1 + cc * 8 + t4 + 4];
            uint4 bq0 = *(const uint4*)&WsFU[((cc * 4 + nq * 2)     * 32 + lane) << 2];
            uint4 bq1 = *(const uint4*)&WsFU[((cc * 4 + nq * 2 + 1) * 32 + lane) << 2];
            MMA_BF16(acc[0][0], acc[0][1], acc[0][2], acc[0][3],
                     a0, a1, a2, a3, bq0.x, bq0.y);
            MMA_BF16(acc[1][0], acc[1][1], acc[1][2], acc[1][3],
                     a0, a1, a2, a3, bq0.z, bq0.w);
            MMA_BF16(acc[2][0], acc[2][1], acc[2][2], acc[2][3],
                     a0, a1, a2, a3, bq1.x, bq1.y);
            MMA_BF16(acc[3][0], acc[3][1], acc[3][2], acc[3][3],
                     a0, a1, a2, a3, bq1.z, bq1.w);
        }

        // ---- dump fragments to Cs ----
        #pragma unroll
        for (int q = 0; q < 4; q++) {
            int col = (nq * 4 + q) * 8 + 2 * t4;
            int rw = mi * 16 + g;
            *(float2*)&Cs[rw * 68 + col]       = make_float2(acc[q][0], acc[q][1]);
            *(float2*)&Cs[(rw + 8) * 68 + col] = make_float2(acc[q][2], acc[q][3]);
        }
        __syncthreads();

        // ---- gate epilogue: 4 outputs per thread (batch be, units jq*4..+3) ----
        {
            float4 ci = *(const float4*)&Cs[be * 68 +  0 + jq * 4];
            float4 cf = *(const float4*)&Cs[be * 68 + 16 + jq * 4];
            float4 cg = *(const float4*)&Cs[be * 68 + 32 + jq * 4];
            float4 co = *(const float4*)&Cs[be * 68 + 48 + jq * 4];
            float4 cell = *(const float4*)&cellc[be * 16 + jq * 4];
            float4 cn, hn;
            cn.x = sigf(cf.x + zf.x) * cell.x + sigf(ci.x + zi.x) * ssf(cg.x + zg.x);
            cn.y = sigf(cf.y + zf.y) * cell.y + sigf(ci.y + zi.y) * ssf(cg.y + zg.y);
            cn.z = sigf(cf.z + zf.z) * cell.z + sigf(ci.z + zi.z) * ssf(cg.z + zg.z);
            cn.w = sigf(cf.w + zf.w) * cell.w + sigf(ci.w + zi.w) * ssf(cg.w + zg.w);
            hn.x = sigf(co.x + zo.x) * ssf(cn.x);
            hn.y = sigf(co.y + zo.y) * ssf(cn.y);
            hn.z = sigf(co.z + zo.z) * ssf(cn.z);
            hn.w = sigf(co.w + zo.w) * ssf(cn.w);
            *(float4*)&cellc[be * 16 + jq * 4] = cn;
            *(float4*)&hallOut[((long)d * TBT + (long)be * TT + t) * UU + u0 + jq * 4] = hn;
            __nv_bfloat162 p0, p1;
            p0.x = __float2bfloat16_rn(hn.x); p0.y = __float2bfloat16_rn(hn.y);
            p1.x = __float2bfloat16_rn(hn.z); p1.y = __float2bfloat16_rn(hn.w);
            uint2 pk = make_uint2(*(uint32_t*)&p0, *(uint32_t*)&p1);
            *(uint2*)&g_hbf[((long)(d * 2 + (t & 1)) * BB + be) * UU + u0 + jq * 4] = pk;
        }

        // ---- signal h_t complete ----
        __threadfence();
        __syncthreads();
        if (tid == 0) atomicAdd(&g_cnt[d * TT + t], 1);
    }
}

__global__ void zero_cnt() {
    int i = blockIdx.x * 256 + threadIdx.x;
    if (i < 2 * TT) g_cnt[i] = 0;
}

__global__ void enc_avg() {
    size_t i = (size_t)blockIdx.x * blockDim.x + threadIdx.x;
    if (i < (size_t)TBT * UU)
        g_enc[i] = 0.5f * (g_hall1[i] + g_hall1[(size_t)TBT * UU + i]);
}

// ---------------- attention scores ----------------
__global__ __launch_bounds__(256) void att_scores(
    const float* __restrict__ Wa0, const float* __restrict__ ba0,
    const float* __restrict__ alpha_a, const float* __restrict__ Wa1,
    const float* __restrict__ ba1)
{
    const int b = blockIdx.x;
    const int t0 = blockIdx.y * 16;
    __shared__ float encsT[512][16];
    __shared__ float red[256];
    const int tid = threadIdx.x;

    for (int i = tid; i < 16 * 512; i += 256) {
        int tt = i >> 9, u = i & 511;
        encsT[u][tt] = g_enc[((size_t)b * TT + t0 + tt) * UU + u];
    }
    __syncthreads();

    float a[16];
    float bb = ba0[tid];
    #pragma unroll
    for (int q = 0; q < 16; q++) a[q] = bb;

    for (int u = 0; u < 512; u++) {
        float w = Wa0[u * 256 + tid];
        const float4* row = (const float4*)encsT[u];
        float4 e0 = row[0], e1 = row[1], e2 = row[2], e3 = row[3];
        a[0]  += e0.x * w; a[1]  += e0.y * w; a[2]  += e0.z * w; a[3]  += e0.w * w;
        a[4]  += e1.x * w; a[5]  += e1.y * w; a[6]  += e1.z * w; a[7]  += e1.w * w;
        a[8]  += e2.x * w; a[9]  += e2.y * w; a[10] += e2.z * w; a[11] += e2.w * w;
        a[12] += e3.x * w; a[13] += e3.y * w; a[14] += e3.z * w; a[15] += e3.w * w;
    }

    float al = alpha_a[tid], w1 = Wa1[tid], b1v = ba1[0];
    for (int q = 0; q < 16; q++) {
        float v = a[q];
        v = (v >= 0.f) ? v : al * v;
        v *= w1;
        red[tid] = v; __syncthreads();
        for (int s = 128; s > 0; s >>= 1) {
            if (tid < s) red[tid] += red[tid + s];
            __syncthreads();
        }
        if (tid == 0) g_scores[b * TT + t0 + q] = red[0] + b1v;
        __syncthreads();
    }
}

// ---------------- softmax over T + weighted pooling ----------------
__global__ __launch_bounds__(256) void softmax_pool() {
    const int b = blockIdx.x;
    const int tid = threadIdx.x;
    __shared__ float ws[256];
    __shared__ float red[256];

    float s = g_scores[b * TT + tid];
    red[tid] = s; __syncthreads();
    for (int st = 128; st > 0; st >>= 1) {
        if (tid < st) red[tid] = fmaxf(red[tid], red[tid + st]);
        __syncthreads();
    }
    float mx = red[0]; __syncthreads();
    float e = expf(s - mx);
    red[tid] = e; __syncthreads();
    for (int st = 128; st > 0; st >>= 1) {
        if (tid < st) red[tid] += red[tid + st];
        __syncthreads();
    }
    float sum = red[0]; __syncthreads();
    ws[tid] = e / sum;
    __syncthreads();

    for (int u = tid; u < UU; u += 256) {
        float acc = 0.f;
        for (int t = 0; t < TT; t++)
            acc += g_enc[((size_t)b * TT + t) * UU + u] * ws[t];
        g_pooled[b * UU + u] = acc;
    }
}

// ---------------- classification head ----------------
__global__ __launch_bounds__(256) void head(
    const float* __restrict__ Wd0, const float* __restrict__ bd0,
    const float* __restrict__ gamma, const float* __restrict__ beta,
    const float* __restrict__ bnm, const float* __restrict__ bnv,
    const float* __restrict__ alpha_h, const float* __restrict__ Wd1,
    const float* __restrict__ bd1, float* __restrict__ out)
{
    const int b = blockIdx.x, j = threadIdx.x;
    __shared__ float ps[512];
    __shared__ float hs[256];
    __shared__ float lgs[7];

    for (int u = j; u < 512; u += 256) ps[u] = g_pooled[b * UU + u];
    __syncthreads();

    float h = bd0[j];
    for (int u = 0; u < 512; u++) h += ps[u] * Wd0[u * 256 + j];
    h = (h - bnm[j]) * rsqrtf(bnv[j] + 1e-3f) * gamma[j] + beta[j];
    h = (h >= 0.f) ? h : alpha_h[j] * h;
    hs[j] = h;
    __syncthreads();

    if (j < 7) {
        float lg = bd1[j];
        for (int k = 0; k < 256; k++) lg += hs[k] * Wd1[k * 7 + j];
        lgs[j] = lg;
    }
    __syncthreads();
    if (j == 0) {
        float mx = lgs[0];
        for (int l = 1; l < 7; l++) mx = fmaxf(mx, lgs[l]);
        float sum = 0.f, e[7];
        for (int l = 0; l < 7; l++) { e[l] = expf(lgs[l] - mx); sum += e[l]; }
        for (int l = 0; l < 7; l++) out[b * 7 + l] = e[l] / sum;
    }
}

// ---------------- driver ----------------
extern "C" void kernel_launch(void* const* d_in, const int* in_sizes, int n_in,
                              void* d_out, int out_size)
{
    const int*   ids   = (const int*)  d_in[0];
    const float* emb   = (const float*)d_in[1];
    const float* k0    = (const float*)d_in[2];
    const float* k12   = (const float*)d_in[3];
    const float* rec   = (const float*)d_in[4];
    const float* bias  = (const float*)d_in[5];
    const float* Wa0   = (const float*)d_in[6];
    const float* ba0   = (const float*)d_in[7];
    const float* al_a  = (const float*)d_in[8];
    const float* Wa1   = (const float*)d_in[9];
    const float* ba1   = (const float*)d_in[10];
    const float* Wd0   = (const float*)d_in[11];
    const float* bd0   = (const float*)d_in[12];
    const float* gamma = (const float*)d_in[13];
    const float* beta  = (const float*)d_in[14];
    const float* bnm   = (const float*)d_in[15];
    const float* bnv   = (const float*)d_in[16];
    const float* al_h  = (const float*)d_in[17];
    const float* Wd1   = (const float*)d_in[18];
    const float* bd1   = (const float*)d_in[19];
    float* out = (float*)d_out;

    cudaFuncSetAttribute((const void*)lstm_layer,
                         cudaFuncAttributeMaxDynamicSharedMemorySize, LSTM_SMEM_BYTES);

    dim3 ggrid(M2 / 128, GG / 64);   // (256, 32)

    gemm_mma<<<ggrid, 256>>>(ids, emb, k0, (long)EE * GG, bias, (long)3 * GG, EE, 0);

    for (int l = 0; l < 3; l++) {
        if (l == 1)
            gemm_mma<<<ggrid, 256>>>(ids, emb, k12, (long)2 * UU * GG,
                                     bias + GG, (long)3 * GG, UU, 1);
        if (l == 2)
            gemm_mma<<<ggrid, 256>>>(ids, emb, k12 + (long)UU * GG, (long)2 * UU * GG,
                                     bias + 2 * GG, (long)3 * GG, UU, 2);
        zero_cnt<<<2, 256>>>();
        float* dstp; cudaGetSymbolAddress((void**)&dstp, (l == 1) ? g_hall2 : g_hall1);
        lstm_layer<<<64, 256, LSTM_SMEM_BYTES>>>(rec + (long)l * UU * GG, dstp);
    }

    enc_avg<<<(int)(((size_t)TBT * UU + 255) / 256), 256>>>();
    att_scores<<<dim3(BB, TT / 16), 256>>>(Wa0, ba0, al_a, Wa1, ba1);
    softmax_pool<<<BB, 256>>>();
    head<<<BB, 256>>>(Wd0, bd0, gamma, beta, bnm, bnv, al_h, Wd1, bd1, out);
}

// round 5
// speedup vs baseline: 3.7692x; 1.0175x over previous
#include <cuda_runtime.h>
#include <cuda_bf16.h>
#include <math.h>
#include <stdint.h>

#define BB 64
#define TT 256
#define EE 300
#define UU 512
#define GG 2048
#define TBT (BB*TT)     /* 16384 rows per direction */
#define M2  (2*TBT)     /* 32768 total rows */

// ---------------- device scratch (static allocation only) ----------------
__device__ float g_z[(size_t)M2 * GG];            // [2][B][T][4U]
__device__ float g_hall1[(size_t)2 * TBT * UU];   // [2][B][T][U]
__device__ float g_hall2[(size_t)2 * TBT * UU];   // [2][B][T][U]
__device__ float g_enc[(size_t)TBT * UU];         // [B][T][U]
__device__ float g_scores[TBT];                   // [B][T]
__device__ float g_pooled[BB * UU];               // [B][U]
__device__ int   g_cnt[2 * TT];                   // per-dir per-step arrival counters
__device__ __nv_bfloat16 g_hbf[2 * 2 * BB * UU];  // [dir][parity][B][U] bf16 h

__device__ __forceinline__ float sigf(float x) { return 1.f / (1.f + __expf(-x)); }
__device__ __forceinline__ float ssf(float x)  { return x / (1.f + fabsf(x)); }

__device__ __forceinline__ float to_tf32(float x) {
    uint32_t u; asm("cvt.rna.tf32.f32 %0, %1;" : "=r"(u) : "f"(x));
    return __uint_as_float(u);
}
__device__ __forceinline__ uint32_t fu(float x) { return __float_as_uint(x); }

#define MMA_TF32(d0,d1,d2,d3,a0,a1,a2,a3,b0,b1) \
    asm volatile("mma.sync.aligned.m16n8k8.row.col.f32.tf32.tf32.f32 " \
        "{%0,%1,%2,%3}, {%4,%5,%6,%7}, {%8,%9}, {%0,%1,%2,%3};" \
        : "+f"(d0), "+f"(d1), "+f"(d2), "+f"(d3) \
        : "r"(a0), "r"(a1), "r"(a2), "r"(a3), "r"(b0), "r"(b1))

#define MMA_BF16(d0,d1,d2,d3,a0,a1,a2,a3,b0,b1) \
    asm volatile("mma.sync.aligned.m16n8k16.row.col.f32.bf16.bf16.f32 " \
        "{%0,%1,%2,%3}, {%4,%5,%6,%7}, {%8,%9}, {%0,%1,%2,%3};" \
        : "+f"(d0), "+f"(d1), "+f"(d2), "+f"(d3) \
        : "r"(a0), "r"(a1), "r"(a2), "r"(a3), "r"(b0), "r"(b1))

// ================= big GEMM via tf32 mma: g_z = A @ Bmat + bias =================
__global__ __launch_bounds__(256) void gemm_mma(
    const int* __restrict__ ids, const float* __restrict__ emb,
    const float* __restrict__ Bbase, long Bstride,
    const float* __restrict__ biasBase, long biasStride,
    int K, int asel)
{
    __shared__ float As[128 * 36];
    __shared__ float Bs[32 * 72];
    __shared__ const float* rowp[128];

    const int m0 = blockIdx.x * 128;
    const int n0 = blockIdx.y * 64;
    const int d  = m0 / TBT;
    const float* Bmat = Bbase + (long)d * Bstride;
    const float* bias = biasBase + (long)d * biasStride;
    const int tid = threadIdx.x;

    if (tid < 128) {
        int m = m0 + tid;
        if (asel == 0) {
            int bt = m % TBT;
            int b = bt / TT, t = bt % TT;
            int tt = d ? (TT - 1 - t) : t;
            rowp[tid] = emb + (long)ids[b * TT + tt] * EE;
        } else {
            const float* hall = (asel == 1) ? g_hall1 : g_hall2;
            rowp[tid] = hall + (long)m * UU;
        }
    }
    __syncthreads();

    const int w = tid >> 5, lane = tid & 31;
    const int g = lane >> 2, t4 = lane & 3;
    const int mw = (w >> 1) * 32;
    const int nw = (w & 1) * 32;

    float acc[2][4][4];
    #pragma unroll
    for (int a = 0; a < 2; a++)
        #pragma unroll
        for (int b = 0; b < 4; b++)
            #pragma unroll
            for (int c = 0; c < 4; c++) acc[a][b][c] = 0.f;

    float4 aP[4], bP[2];
    const int nch = (K + 31) >> 5;

    auto ldA = [&](int kb) {
        bool full = (kb + 32) <= K;
        #pragma unroll
        for (int i = 0; i < 4; i++) {
            int idx = tid + i * 256;
            int row = idx >> 3, c4 = idx & 7;
            if (full) {
                aP[i] = *(const float4*)(rowp[row] + kb + c4 * 4);
            } else {
                float v[4];
                #pragma unroll
                for (int q = 0; q < 4; q++) {
                    int k = kb + c4 * 4 + q;
                    v[q] = (k < K) ? rowp[row][k] : 0.f;
                }
                aP[i] = make_float4(v[0], v[1], v[2], v[3]);
            }
        }
    };
    auto ldB = [&](int kb) {
        #pragma unroll
        for (int i = 0; i < 2; i++) {
            int idx = tid + i * 256;
            int kr = idx >> 4, c4 = idx & 15;
            int k = kb + kr;
            if (k < K) bP[i] = *(const float4*)(Bmat + (long)k * GG + n0 + c4 * 4);
            else       bP[i] = make_float4(0.f, 0.f, 0.f, 0.f);
        }
    };

    ldA(0); ldB(0);

    for (int c = 0; c < nch; c++) {
        __syncthreads();
        #pragma unroll
        for (int i = 0; i < 4; i++) {
            int idx = tid + i * 256;
            int row = idx >> 3, c4 = idx & 7;
            float4 v = aP[i];
            *(float4*)&As[row * 36 + c4 * 4] =
                make_float4(to_tf32(v.x), to_tf32(v.y), to_tf32(v.z), to_tf32(v.w));
        }
        #pragma unroll
        for (int i = 0; i < 2; i++) {
            int idx = tid + i * 256;
            int kr = idx >> 4, c4 = idx & 15;
            float4 v = bP[i];
            *(float4*)&Bs[kr * 72 + c4 * 4] =
                make_float4(to_tf32(v.x), to_tf32(v.y), to_tf32(v.z), to_tf32(v.w));
        }
        __syncthreads();
        if (c + 1 < nch) { ldA((c + 1) * 32); ldB((c + 1) * 32); }

        #pragma unroll
        for (int kk = 0; kk < 32; kk += 8) {
            uint32_t a[2][4];
            #pragma unroll
            for (int mt = 0; mt < 2; mt++) {
                int rb = mw + mt * 16;
                a[mt][0] = fu(As[(rb + g)     * 36 + kk + t4]);
                a[mt][1] = fu(As[(rb + 8 + g) * 36 + kk + t4]);
                a[mt][2] = fu(As[(rb + g)     * 36 + kk + t4 + 4]);
                a[mt][3] = fu(As[(rb + 8 + g) * 36 + kk + t4 + 4]);
            }
            #pragma unroll
            for (int nt = 0; nt < 4; nt++) {
                uint32_t b0 = fu(Bs[(kk + t4)     * 72 + nw + nt * 8 + g]);
                uint32_t b1 = fu(Bs[(kk + t4 + 4) * 72 + nw + nt * 8 + g]);
                MMA_TF32(acc[0][nt][0], acc[0][nt][1], acc[0][nt][2], acc[0][nt][3],
                         a[0][0], a[0][1], a[0][2], a[0][3], b0, b1);
                MMA_TF32(acc[1][nt][0], acc[1][nt][1], acc[1][nt][2], acc[1][nt][3],
                         a[1][0], a[1][1], a[1][2], a[1][3], b0, b1);
            }
        }
    }

    #pragma unroll
    for (int mt = 0; mt < 2; mt++) {
        #pragma unroll
        for (int nt = 0; nt < 4; nt++) {
            int col = n0 + nw + nt * 8 + 2 * t4;
            float b0 = bias[col], b1 = bias[col + 1];
            long r0 = (long)m0 + mw + mt * 16 + g;
            *(float2*)&g_z[r0 * GG + col] =
                make_float2(acc[mt][nt][0] + b0, acc[mt][nt][1] + b1);
            *(float2*)&g_z[(r0 + 8) * GG + col] =
                make_float2(acc[mt][nt][2] + b0, acc[mt][nt][3] + b1);
        }
    }
}

// ================= persistent LSTM layer, bf16 mma version =================
// 64 blocks: d = bx>>5, slice = bx&31 -> 16 units (64 gate cols).
// 256 threads = 8 warps. C tile = 64(batch) x 64(gate cols).
// Warp w: mi = w>>1 (batch 16-rows), nq = w&1 (4 of 8 n-tiles).
// SMEM: WsFU  bf16 weight fragments  64KB   (staged once per layer)
//       As16  h_{t-1} bf16 [64][520] 66.5KB (staged per step from g_hbf)
//       Cs    fp32 [64][68]          17.4KB
//       cellc fp32 [64][16]           4KB
#define LSTM_SMEM_BYTES (65536 + 66560 + 17408 + 4096)

__global__ __launch_bounds__(256) void lstm_layer(
    const float* __restrict__ recLayer,   // rec + l*U*GG  (dir stride 3*U*GG)
    float* __restrict__ hallOut)
{
    extern __shared__ char smraw[];
    uint32_t*      WsFU  = (uint32_t*)smraw;                          // 16384 u32
    __nv_bfloat16* As16  = (__nv_bfloat16*)(smraw + 65536);           // 64*520
    uint32_t*      AsU   = (uint32_t*)As16;                           // stride 260
    float*         Cs    = (float*)(smraw + 65536 + 66560);           // 64*68
    float*         cellc = (float*)(smraw + 65536 + 66560 + 17408);   // 64*16

    const int bx = blockIdx.x;
    const int d  = bx >> 5;
    const int u0 = (bx & 31) * 16;
    const float* rec = recLayer + (long)d * 3 * UU * GG;
    const int tid = threadIdx.x;

    // ---- stage weight fragments (once per layer) ----
    // slot i -> chunk cc, ntile nt, lane; stores b0 (k 2t4,2t4+1) and b1 (k+8)
    for (int i = tid; i < 32 * 8 * 32; i += 256) {
        int cc = i >> 8;
        int rem = i & 255;
        int nt = rem >> 5;
        int lane = rem & 31;
        int gq = lane >> 2, t4 = lane & 3;
        int col = nt * 8 + gq;                 // 0..63
        long wcol = (long)(col >> 4) * UU + u0 + (col & 15);
        int k0 = cc * 16 + 2 * t4;
        __nv_bfloat162 b0, b1;
        b0.x = __float2bfloat16_rn(rec[(long)k0 * GG + wcol]);
        b0.y = __float2bfloat16_rn(rec[(long)(k0 + 1) * GG + wcol]);
        b1.x = __float2bfloat16_rn(rec[(long)(k0 + 8) * GG + wcol]);
        b1.y = __float2bfloat16_rn(rec[(long)(k0 + 9) * GG + wcol]);
        uint32_t* dst = WsFU + (((cc * 4 + (nt >> 1)) * 32 + lane) << 2) + (nt & 1) * 2;
        dst[0] = *(uint32_t*)&b0;
        dst[1] = *(uint32_t*)&b1;
    }
    for (int i = tid; i < 64 * 16; i += 256) cellc[i] = 0.f;
    __syncthreads();

    const int w = tid >> 5, lane = tid & 31;
    const int g = lane >> 2, t4 = lane & 3;
    const int mi = w >> 1;        // batch 16-row tile
    const int nq = w & 1;         // which 4 n-tiles

    const int be = tid & 63;      // epilogue batch row
    const int jq = tid >> 6;      // epilogue unit quad (4 units)

    for (int t = 0; t < TT; t++) {
        // ---- prefetch z for this step (independent of barrier) ----
        long zbase = ((long)d * TBT + (long)be * TT + t) * GG + u0 + jq * 4;
        float4 zi = *(const float4*)&g_z[zbase];
        float4 zf = *(const float4*)&g_z[zbase + UU];
        float4 zg = *(const float4*)&g_z[zbase + 2 * UU];
        float4 zo = *(const float4*)&g_z[zbase + 3 * UU];

        // ---- wait for h_{t-1} from all 32 blocks of this dir ----
        if (t > 0) {
            if (tid == 0) {
                volatile int* p = &g_cnt[d * TT + (t - 1)];
                while (*p < 32) __nanosleep(32);
                __threadfence();
            }
            __syncthreads();
        }

        // ---- stage A = h_{t-1} bf16 [64][512] ----
        if (t == 0) {
            uint4 z4 = make_uint4(0, 0, 0, 0);
            for (int i = tid; i < 64 * 64; i += 256) {
                int row = i >> 6, c8 = i & 63;
                *(uint4*)(As16 + row * 520 + c8 * 8) = z4;
            }
        } else {
            const int par = (t - 1) & 1;
            const __nv_bfloat16* hb = g_hbf + ((long)(d * 2 + par) * BB) * UU;
            #pragma unroll
            for (int i = 0; i < 16; i++) {
                int idx = tid + i * 256;
                int row = idx >> 6, c8 = idx & 63;
                uint4 v = *(const uint4*)(hb + row * UU + c8 * 8);
                *(uint4*)(As16 + row * 520 + c8 * 8) = v;
            }
        }
        __syncthreads();

        // ---- mma: [64x512] @ [512x64], bf16 m16n8k16 ----
        float acc[4][4];
        #pragma unroll
        for (int q = 0; q < 4; q++)
            #pragma unroll
            for (int r = 0; r < 4; r++) acc[q][r] = 0.f;

        const int ar0 = (mi * 16 + g) * 260;
        const int ar1 = ar0 + 8 * 260;
        #pragma unroll 4
        for (int cc = 0; cc < 32; cc++) {
            uint32_t a0 = AsU[ar0 + cc * 8 + t4];
            uint32_t a1 = AsU[ar1 + cc * 8 + t4];
            uint32_t a2 = AsU[ar0 + cc * 8 + t4 + 4];
            uint32_t a3 = AsU[ar1 + cc * 8 + t4 + 4];
            uint4 bq0 = *(const uint4*)&WsFU[((cc * 4 + nq * 2)     * 32 + lane) << 2];
            uint4 bq1 = *(const uint4*)&WsFU[((cc * 4 + nq * 2 + 1) * 32 + lane) << 2];
            MMA_BF16(acc[0][0], acc[0][1], acc[0][2], acc[0][3],
                     a0, a1, a2, a3, bq0.x, bq0.y);
            MMA_BF16(acc[1][0], acc[1][1], acc[1][2], acc[1][3],
                     a0, a1, a2, a3, bq0.z, bq0.w);
            MMA_BF16(acc[2][0], acc[2][1], acc[2][2], acc[2][3],
                     a0, a1, a2, a3, bq1.x, bq1.y);
            MMA_BF16(acc[3][0], acc[3][1], acc[3][2], acc[3][3],
                     a0, a1, a2, a3, bq1.z, bq1.w);
        }

        // ---- dump fragments to Cs ----
        #pragma unroll
        for (int q = 0; q < 4; q++) {
            int col = (nq * 4 + q) * 8 + 2 * t4;
            int rw = mi * 16 + g;
            *(float2*)&Cs[rw * 68 + col]       = make_float2(acc[q][0], acc[q][1]);
            *(float2*)&Cs[(rw + 8) * 68 + col] = make_float2(acc[q][2], acc[q][3]);
        }
        __syncthreads();

        // ---- gate epilogue: 4 outputs per thread (batch be, units jq*4..+3) ----
        {
            float4 ci = *(const float4*)&Cs[be * 68 +  0 + jq * 4];
            float4 cf = *(const float4*)&Cs[be * 68 + 16 + jq * 4];
            float4 cg = *(const float4*)&Cs[be * 68 + 32 + jq * 4];
            float4 co = *(const float4*)&Cs[be * 68 + 48 + jq * 4];
            float4 cell = *(const float4*)&cellc[be * 16 + jq * 4];
            float4 cn, hn;
            cn.x = sigf(cf.x + zf.x) * cell.x + sigf(ci.x + zi.x) * ssf(cg.x + zg.x);
            cn.y = sigf(cf.y + zf.y) * cell.y + sigf(ci.y + zi.y) * ssf(cg.y + zg.y);
            cn.z = sigf(cf.z + zf.z) * cell.z + sigf(ci.z + zi.z) * ssf(cg.z + zg.z);
            cn.w = sigf(cf.w + zf.w) * cell.w + sigf(ci.w + zi.w) * ssf(cg.w + zg.w);
            hn.x = sigf(co.x + zo.x) * ssf(cn.x);
            hn.y = sigf(co.y + zo.y) * ssf(cn.y);
            hn.z = sigf(co.z + zo.z) * ssf(cn.z);
            hn.w = sigf(co.w + zo.w) * ssf(cn.w);
            *(float4*)&cellc[be * 16 + jq * 4] = cn;
            *(float4*)&hallOut[((long)d * TBT + (long)be * TT + t) * UU + u0 + jq * 4] = hn;
            __nv_bfloat162 p0, p1;
            p0.x = __float2bfloat16_rn(hn.x); p0.y = __float2bfloat16_rn(hn.y);
            p1.x = __float2bfloat16_rn(hn.z); p1.y = __float2bfloat16_rn(hn.w);
            uint2 pk = make_uint2(*(uint32_t*)&p0, *(uint32_t*)&p1);
            *(uint2*)&g_hbf[((long)(d * 2 + (t & 1)) * BB + be) * UU + u0 + jq * 4] = pk;
        }

        // ---- signal h_t complete ----
        __threadfence();
        __syncthreads();
        if (tid == 0) atomicAdd(&g_cnt[d * TT + t], 1);
    }
}

__global__ void zero_cnt() {
    int i = blockIdx.x * 256 + threadIdx.x;
    if (i < 2 * TT) g_cnt[i] = 0;
}

__global__ void enc_avg() {
    size_t i = (size_t)blockIdx.x * blockDim.x + threadIdx.x;
    if (i < (size_t)TBT * UU)
        g_enc[i] = 0.5f * (g_hall1[i] + g_hall1[(size_t)TBT * UU + i]);
}

// ---------------- attention scores ----------------
__global__ __launch_bounds__(256) void att_scores(
    const float* __restrict__ Wa0, const float* __restrict__ ba0,
    const float* __restrict__ alpha_a, const float* __restrict__ Wa1,
    const float* __restrict__ ba1)
{
    const int b = blockIdx.x;
    const int t0 = blockIdx.y * 16;
    __shared__ float encsT[512][16];
    __shared__ float red[256];
    const int tid = threadIdx.x;

    for (int i = tid; i < 16 * 512; i += 256) {
        int tt = i >> 9, u = i & 511;
        encsT[u][tt] = g_enc[((size_t)b * TT + t0 + tt) * UU + u];
    }
    __syncthreads();

    float a[16];
    float bb = ba0[tid];
    #pragma unroll
    for (int q = 0; q < 16; q++) a[q] = bb;

    for (int u = 0; u < 512; u++) {
        float w = Wa0[u * 256 + tid];
        const float4* row = (const float4*)encsT[u];
        float4 e0 = row[0], e1 = row[1], e2 = row[2], e3 = row[3];
        a[0]  += e0.x * w; a[1]  += e0.y * w; a[2]  += e0.z * w; a[3]  += e0.w * w;
        a[4]  += e1.x * w; a[5]  += e1.y * w; a[6]  += e1.z * w; a[7]  += e1.w * w;
        a[8]  += e2.x * w; a[9]  += e2.y * w; a[10] += e2.z * w; a[11] += e2.w * w;
        a[12] += e3.x * w; a[13] += e3.y * w; a[14] += e3.z * w; a[15] += e3.w * w;
    }

    float al = alpha_a[tid], w1 = Wa1[tid], b1v = ba1[0];
    for (int q = 0; q < 16; q++) {
        float v = a[q];
        v = (v >= 0.f) ? v : al * v;
        v *= w1;
        red[tid] = v; __syncthreads();
        for (int s = 128; s > 0; s >>= 1) {
            if (tid < s) red[tid] += red[tid + s];
            __syncthreads();
        }
        if (tid == 0) g_scores[b * TT + t0 + q] = red[0] + b1v;
        __syncthreads();
    }
}

// ---------------- softmax over T + weighted pooling ----------------
__global__ __launch_bounds__(256) void softmax_pool() {
    const int b = blockIdx.x;
    const int tid = threadIdx.x;
    __shared__ float ws[256];
    __shared__ float red[256];

    float s = g_scores[b * TT + tid];
    red[tid] = s; __syncthreads();
    for (int st = 128; st > 0; st >>= 1) {
        if (tid < st) red[tid] = fmaxf(red[tid], red[tid + st]);
        __syncthreads();
    }
    float mx = red[0]; __syncthreads();
    float e = expf(s - mx);
    red[tid] = e; __syncthreads();
    for (int st = 128; st > 0; st >>= 1) {
        if (tid < st) red[tid] += red[tid + st];
        __syncthreads();
    }
    float sum = red[0]; __syncthreads();
    ws[tid] = e / sum;
    __syncthreads();

    for (int u = tid; u < UU; u += 256) {
        float acc = 0.f;
        for (int t = 0; t < TT; t++)
            acc += g_enc[((size_t)b * TT + t) * UU + u] * ws[t];
        g_pooled[b * UU + u] = acc;
    }
}

// ---------------- classification head ----------------
__global__ __launch_bounds__(256) void head(
    const float* __restrict__ Wd0, const float* __restrict__ bd0,
    const float* __restrict__ gamma, const float* __restrict__ beta,
    const float* __restrict__ bnm, const float* __restrict__ bnv,
    const float* __restrict__ alpha_h, const float* __restrict__ Wd1,
    const float* __restrict__ bd1, float* __restrict__ out)
{
    const int b = blockIdx.x, j = threadIdx.x;
    __shared__ float ps[512];
    __shared__ float hs[256];
    __shared__ float lgs[7];

    for (int u = j; u < 512; u += 256) ps[u] = g_pooled[b * UU + u];
    __syncthreads();

    float h = bd0[j];
    for (int u = 0; u < 512; u++) h += ps[u] * Wd0[u * 256 + j];
    h = (h - bnm[j]) * rsqrtf(bnv[j] + 1e-3f) * gamma[j] + beta[j];
    h = (h >= 0.f) ? h : alpha_h[j] * h;
    hs[j] = h;
    __syncthreads();

    if (j < 7) {
        float lg = bd1[j];
        for (int k = 0; k < 256; k++) lg += hs[k] * Wd1[k * 7 + j];
        lgs[j] = lg;
    }
    __syncthreads();
    if (j == 0) {
        float mx = lgs[0];
        for (int l = 1; l < 7; l++) mx = fmaxf(mx, lgs[l]);
        float sum = 0.f, e[7];
        for (int l = 0; l < 7; l++) { e[l] = expf(lgs[l] - mx); sum += e[l]; }
        for (int l = 0; l < 7; l++) out[b * 7 + l] = e[l] / sum;
    }
}

// ---------------- driver ----------------
extern "C" void kernel_launch(void* const* d_in, const int* in_sizes, int n_in,
                              void* d_out, int out_size)
{
    const int*   ids   = (const int*)  d_in[0];
    const float* emb   = (const float*)d_in[1];
    const float* k0    = (const float*)d_in[2];
    const float* k12   = (const float*)d_in[3];
    const float* rec   = (const float*)d_in[4];
    const float* bias  = (const float*)d_in[5];
    const float* Wa0   = (const float*)d_in[6];
    const float* ba0   = (const float*)d_in[7];
    const float* al_a  = (const float*)d_in[8];
    const float* Wa1   = (const float*)d_in[9];
    const float* ba1   = (const float*)d_in[10];
    const float* Wd0   = (const float*)d_in[11];
    const float* bd0   = (const float*)d_in[12];
    const float* gamma = (const float*)d_in[13];
    const float* beta  = (const float*)d_in[14];
    const float* bnm   = (const float*)d_in[15];
    const float* bnv   = (const float*)d_in[16];
    const float* al_h  = (const float*)d_in[17];
    const float* Wd1   = (const float*)d_in[18];
    const float* bd1   = (const float*)d_in[19];
    float* out = (float*)d_out;

    cudaFuncSetAttribute((const void*)lstm_layer,
                         cudaFuncAttributeMaxDynamicSharedMemorySize, LSTM_SMEM_BYTES);

    dim3 ggrid(M2 / 128, GG / 64);   // (256, 32)

    gemm_mma<<<ggrid, 256>>>(ids, emb, k0, (long)EE * GG, bias, (long)3 * GG, EE, 0);

    for (int l = 0; l < 3; l++) {
        if (l == 1)
            gemm_mma<<<ggrid, 256>>>(ids, emb, k12, (long)2 * UU * GG,
                                     bias + GG, (long)3 * GG, UU, 1);
        if (l == 2)
            gemm_mma<<<ggrid, 256>>>(ids, emb, k12 + (long)UU * GG, (long)2 * UU * GG,
                                     bias + 2 * GG, (long)3 * GG, UU, 2);
        zero_cnt<<<2, 256>>>();
        float* dstp; cudaGetSymbolAddress((void**)&dstp, (l == 1) ? g_hall2 : g_hall1);
        lstm_layer<<<64, 256, LSTM_SMEM_BYTES>>>(rec + (long)l * UU * GG, dstp);
    }

    enc_avg<<<(int)(((size_t)TBT * UU + 255) / 256), 256>>>();
    att_scores<<<dim3(BB, TT / 16), 256>>>(Wa0, ba0, al_a, Wa1, ba1);
    softmax_pool<<<BB, 256>>>();
    head<<<BB, 256>>>(Wd0, bd0, gamma, beta, bnm, bnv, al_h, Wd1, bd1, out);
}